// round 1
// baseline (speedup 1.0000x reference)
#include <cuda_runtime.h>
#include <math.h>

#define CBATCH   4
#define CSEQ     2048
#define CDMODEL  1024
#define CDMAMBA  2048
#define CDSTATE  16
#define CNHEADS  32
#define CMROWS   (CBATCH * CSEQ)          // 8192
#define CNCHUNK  32
#define CLCHUNK  (CSEQ / CNCHUNK)         // 64
#define CHEADDIM (CDMAMBA / CNHEADS)      // 64

// ---------------- scratch (static device arrays; no runtime allocation) ----------------
__device__ float g_xssm[CMROWS * CDMAMBA];                       // 64 MB
__device__ float g_dt  [CMROWS * CDMAMBA];                       // 64 MB
__device__ float g_Bn  [CMROWS * CDSTATE];                       // 0.5 MB
__device__ float g_Cn  [CMROWS * CDSTATE];                       // 0.5 MB
__device__ float g_y   [CMROWS * CDMAMBA];                       // 64 MB
__device__ float g_hloc [CBATCH * CNCHUNK * CDSTATE * CDMAMBA];  // 16 MB
__device__ float g_hinit[CBATCH * CNCHUNK * CDSTATE * CDMAMBA];  // 16 MB
__device__ float g_S    [CBATCH * CNCHUNK * CDMAMBA];            // 1 MB

// ---------------- packed f32x2 helpers (Blackwell FFMA2 — ptxas won't emit these itself) ----
__device__ __forceinline__ unsigned long long pk2(float lo, float hi) {
    unsigned long long r;
    asm("mov.b64 %0, {%1, %2};" : "=l"(r) : "f"(lo), "f"(hi));
    return r;
}
__device__ __forceinline__ void upk2(unsigned long long v, float &lo, float &hi) {
    asm("mov.b64 {%0, %1}, %2;" : "=f"(lo), "=f"(hi) : "l"(v));
}
__device__ __forceinline__ void ffma2(unsigned long long &d, unsigned long long a,
                                      unsigned long long b) {
    asm("fma.rn.f32x2 %0, %1, %2, %0;" : "+l"(d) : "l"(a), "l"(b));
}

__device__ __forceinline__ float dt_transform(float v, float b) {
    v += b;
    v = fminf(fmaxf(v, -10.0f), 5.0f);
    v = log1pf(expf(v));                 // softplus, accurate
    return fminf(fmaxf(v, 1e-4f), 0.1f);
}

// ---------------- SGEMM: C[m,n] = sum_k A[m,k] * W[n,k]  (both K-major) ----------------
// 128x128 tile, BK=16, 256 threads, 8x8 per thread, f32x2 accumulators.
// EPI: 0 = identity, 1 = dt transform (+bias, clip, softplus, clip)
template <int EPI>
__global__ __launch_bounds__(256) void sgemm_abt(const float* __restrict__ A,
                                                 const float* __restrict__ W,
                                                 const float* __restrict__ bias,
                                                 float* __restrict__ C,
                                                 int M, int N, int K) {
    __shared__ float Xs[16 * 128];
    __shared__ float Ws[16 * 128];

    const int tid = threadIdx.x;
    const int tx = tid & 15;     // 0..15 -> column group
    const int ty = tid >> 4;     // 0..15 -> row group
    const int m0 = blockIdx.y * 128;
    const int n0 = blockIdx.x * 128;

    unsigned long long acc[8][4];
#pragma unroll
    for (int i = 0; i < 8; i++)
#pragma unroll
        for (int j = 0; j < 4; j++) acc[i][j] = pk2(0.0f, 0.0f);

    for (int kt = 0; kt < K; kt += 16) {
        // load A and W tiles (transposed into smem: [k][row])
#pragma unroll
        for (int half = 0; half < 2; half++) {
            int q = tid + half * 256;          // 0..511
            int r = q >> 2;                    // 0..127
            int k4 = (q & 3) * 4;              // 0,4,8,12
            float4 va = *reinterpret_cast<const float4*>(&A[(size_t)(m0 + r) * K + kt + k4]);
            Xs[(k4 + 0) * 128 + r] = va.x;
            Xs[(k4 + 1) * 128 + r] = va.y;
            Xs[(k4 + 2) * 128 + r] = va.z;
            Xs[(k4 + 3) * 128 + r] = va.w;
            float4 vw = *reinterpret_cast<const float4*>(&W[(size_t)(n0 + r) * K + kt + k4]);
            Ws[(k4 + 0) * 128 + r] = vw.x;
            Ws[(k4 + 1) * 128 + r] = vw.y;
            Ws[(k4 + 2) * 128 + r] = vw.z;
            Ws[(k4 + 3) * 128 + r] = vw.w;
        }
        __syncthreads();

#pragma unroll
        for (int kk = 0; kk < 16; kk++) {
            float4 a0 = *reinterpret_cast<const float4*>(&Xs[kk * 128 + ty * 8]);
            float4 a1 = *reinterpret_cast<const float4*>(&Xs[kk * 128 + ty * 8 + 4]);
            float av[8] = {a0.x, a0.y, a0.z, a0.w, a1.x, a1.y, a1.z, a1.w};
            unsigned long long ap[8];
#pragma unroll
            for (int i = 0; i < 8; i++) ap[i] = pk2(av[i], av[i]);
            unsigned long long bp[4];
#pragma unroll
            for (int j = 0; j < 4; j++)
                bp[j] = *reinterpret_cast<const unsigned long long*>(
                    &Ws[kk * 128 + (tx + 16 * j) * 2]);
#pragma unroll
            for (int i = 0; i < 8; i++)
#pragma unroll
                for (int j = 0; j < 4; j++) ffma2(acc[i][j], ap[i], bp[j]);
        }
        __syncthreads();
    }

    // epilogue: thread owns rows m0+ty*8+i, column pairs n0 + (tx+16*j)*2
#pragma unroll
    for (int i = 0; i < 8; i++) {
        int m = m0 + ty * 8 + i;
#pragma unroll
        for (int j = 0; j < 4; j++) {
            int n = n0 + (tx + 16 * j) * 2;
            float lo, hi;
            upk2(acc[i][j], lo, hi);
            if (EPI == 1) {
                float2 bb = *reinterpret_cast<const float2*>(&bias[n]);
                lo = dt_transform(lo, bb.x);
                hi = dt_transform(hi, bb.y);
            }
            *reinterpret_cast<float2*>(&C[(size_t)m * N + n]) = make_float2(lo, hi);
        }
    }
}

// ---------------- B/C projection + row normalization ----------------
// one warp per row; lane n<16 computes B[n], lane n>=16 computes C[n-16]
__global__ __launch_bounds__(128) void bc_kernel(const float* __restrict__ X,
                                                 const float* __restrict__ WB,
                                                 const float* __restrict__ WC) {
    int warp = threadIdx.x >> 5;
    int lane = threadIdx.x & 31;
    int m = blockIdx.x * 4 + warp;
    const float* Wr = (lane < 16) ? (WB + (size_t)lane * CDMODEL)
                                  : (WC + (size_t)(lane - 16) * CDMODEL);
    const float* Xr = X + (size_t)m * CDMODEL;

    float4 av = make_float4(0.f, 0.f, 0.f, 0.f);
    for (int k = 0; k < CDMODEL; k += 4) {
        float4 xv = *reinterpret_cast<const float4*>(&Xr[k]);
        float4 wv = *reinterpret_cast<const float4*>(&Wr[k]);
        av.x = fmaf(xv.x, wv.x, av.x);
        av.y = fmaf(xv.y, wv.y, av.y);
        av.z = fmaf(xv.z, wv.z, av.z);
        av.w = fmaf(xv.w, wv.w, av.w);
    }
    float acc = (av.x + av.y) + (av.z + av.w);

    float ss = acc * acc;
#pragma unroll
    for (int off = 8; off >= 1; off >>= 1)
        ss += __shfl_xor_sync(0xffffffffu, ss, off);   // stays within each 16-lane half
    float scale = 1.0f / fmaxf(sqrtf(ss), 1.0f);
    float v = acc * scale;
    if (lane < 16) g_Bn[(size_t)m * 16 + lane] = v;
    else           g_Cn[(size_t)m * 16 + (lane - 16)] = v;
}

__device__ __forceinline__ void load16(const float* p, float* v) {
    const float4* q = reinterpret_cast<const float4*>(p);
    float4 a = q[0], b = q[1], c = q[2], d = q[3];
    v[0] = a.x; v[1] = a.y; v[2] = a.z; v[3] = a.w;
    v[4] = b.x; v[5] = b.y; v[6] = b.z; v[7] = b.w;
    v[8] = c.x; v[9] = c.y; v[10] = c.z; v[11] = c.w;
    v[12] = d.x; v[13] = d.y; v[14] = d.z; v[15] = d.w;
}

// Load A values for channel d; returns true if A_n ~= n+1 (power-chain fast path valid)
__device__ __forceinline__ bool load_A(const float* __restrict__ A_log, int d, float* Av) {
    int head = d / CHEADDIM;
    bool fast = true;
#pragma unroll
    for (int n = 0; n < 16; n++) {
        Av[n] = expf(A_log[head * 16 + n]);
        if (fabsf(Av[n] - (float)(n + 1)) > 1e-3f * (float)(n + 1)) fast = false;
    }
    return fast;
}

// ---------------- scan pass 1: per-chunk local scan -> final h, sum(dt) ----------------
__global__ __launch_bounds__(256) void scan_pass1(const float* __restrict__ A_log) {
    int d = blockIdx.x * 256 + threadIdx.x;
    int c = blockIdx.y;
    int b = blockIdx.z;

    float Av[16];
    bool fastA = load_A(A_log, d, Av);

    float h[16];
#pragma unroll
    for (int n = 0; n < 16; n++) h[n] = 0.0f;
    float S = 0.0f;

    int row0 = b * CSEQ + c * CLCHUNK;
    for (int t = 0; t < CLCHUNK; t++) {
        size_t ro = (size_t)(row0 + t) * CDMAMBA + d;
        float dt = g_dt[ro];
        float x  = g_xssm[ro];
        float Bv[16];
        load16(g_Bn + (size_t)(row0 + t) * 16, Bv);
        S += dt;
        float dtx = dt * x;
        if (fastA) {
            float r = __expf(-dt), p = 1.0f;
#pragma unroll
            for (int n = 0; n < 16; n++) { p *= r; h[n] = fmaf(p, h[n], dtx * Bv[n]); }
        } else {
#pragma unroll
            for (int n = 0; n < 16; n++) {
                float dec = __expf(-dt * Av[n]);
                h[n] = fmaf(dec, h[n], dtx * Bv[n]);
            }
        }
    }
    size_t base = ((size_t)(b * CNCHUNK + c) * 16) * CDMAMBA + d;
#pragma unroll
    for (int n = 0; n < 16; n++) g_hloc[base + (size_t)n * CDMAMBA] = h[n];
    g_S[(size_t)(b * CNCHUNK + c) * CDMAMBA + d] = S;
}

// ---------------- scan pass 2: sequential combine of chunk boundary states ----------------
__global__ __launch_bounds__(256) void scan_pass2(const float* __restrict__ A_log) {
    int idx = blockIdx.x * 256 + threadIdx.x;   // 0..8191
    int b = idx / CDMAMBA;
    int d = idx % CDMAMBA;

    float Av[16];
    bool fastA = load_A(A_log, d, Av);

    float h[16];
#pragma unroll
    for (int n = 0; n < 16; n++) h[n] = 0.0f;

    for (int c = 0; c < CNCHUNK; c++) {
        size_t base = ((size_t)(b * CNCHUNK + c) * 16) * CDMAMBA + d;
#pragma unroll
        for (int n = 0; n < 16; n++) g_hinit[base + (size_t)n * CDMAMBA] = h[n];
        float S = g_S[(size_t)(b * CNCHUNK + c) * CDMAMBA + d];
        if (fastA) {
            float R = __expf(-S), p = 1.0f;
#pragma unroll
            for (int n = 0; n < 16; n++) {
                p *= R;
                h[n] = fmaf(p, h[n], g_hloc[base + (size_t)n * CDMAMBA]);
            }
        } else {
#pragma unroll
            for (int n = 0; n < 16; n++) {
                float P = __expf(-S * Av[n]);
                h[n] = fmaf(P, h[n], g_hloc[base + (size_t)n * CDMAMBA]);
            }
        }
    }
}

// ---------------- scan pass 3: replay chunks with correct h_init, emit y ----------------
__global__ __launch_bounds__(256) void scan_pass3(const float* __restrict__ A_log,
                                                  const float* __restrict__ Dvec) {
    int d = blockIdx.x * 256 + threadIdx.x;
    int c = blockIdx.y;
    int b = blockIdx.z;

    float Av[16];
    bool fastA = load_A(A_log, d, Av);
    float Dd = Dvec[d];

    float h[16];
    size_t base = ((size_t)(b * CNCHUNK + c) * 16) * CDMAMBA + d;
#pragma unroll
    for (int n = 0; n < 16; n++) h[n] = g_hinit[base + (size_t)n * CDMAMBA];

    int row0 = b * CSEQ + c * CLCHUNK;
    for (int t = 0; t < CLCHUNK; t++) {
        size_t ro = (size_t)(row0 + t) * CDMAMBA + d;
        float dt = g_dt[ro];
        float x  = g_xssm[ro];
        float Bv[16], Cv[16];
        load16(g_Bn + (size_t)(row0 + t) * 16, Bv);
        load16(g_Cn + (size_t)(row0 + t) * 16, Cv);
        float dtx = dt * x;
        float y = 0.0f;
        if (fastA) {
            float r = __expf(-dt), p = 1.0f;
#pragma unroll
            for (int n = 0; n < 16; n++) {
                p *= r;
                h[n] = fmaf(p, h[n], dtx * Bv[n]);
                y = fmaf(h[n], Cv[n], y);
            }
        } else {
#pragma unroll
            for (int n = 0; n < 16; n++) {
                float dec = __expf(-dt * Av[n]);
                h[n] = fmaf(dec, h[n], dtx * Bv[n]);
                y = fmaf(h[n], Cv[n], y);
            }
        }
        g_y[ro] = fmaf(x, Dd, y);
    }
}

// ---------------- launch ----------------
extern "C" void kernel_launch(void* const* d_in, const int* in_sizes, int n_in,
                              void* d_out, int out_size) {
    (void)in_sizes; (void)n_in; (void)out_size;
    const float* x_norm     = (const float*)d_in[0];
    const float* x_proj_w   = (const float*)d_in[1];
    const float* dt_proj_w  = (const float*)d_in[2];
    const float* dt_proj_b  = (const float*)d_in[3];
    const float* B_proj_w   = (const float*)d_in[4];
    const float* C_proj_w   = (const float*)d_in[5];
    const float* A_log      = (const float*)d_in[6];
    const float* Dvec       = (const float*)d_in[7];
    const float* out_proj_w = (const float*)d_in[8];
    float* out = (float*)d_out;

    void *p_xssm, *p_dt, *p_y;
    cudaGetSymbolAddress(&p_xssm, g_xssm);
    cudaGetSymbolAddress(&p_dt, g_dt);
    cudaGetSymbolAddress(&p_y, g_y);

    dim3 gemm_grid(CDMAMBA / 128, CMROWS / 128);   // (16, 64)

    // 1) x_ssm = x_norm @ x_proj_w^T
    sgemm_abt<0><<<gemm_grid, 256>>>(x_norm, x_proj_w, nullptr, (float*)p_xssm,
                                     CMROWS, CDMAMBA, CDMODEL);
    // 2) dt = clip(softplus(clip(x_norm @ dt_proj_w^T + b)))
    sgemm_abt<1><<<gemm_grid, 256>>>(x_norm, dt_proj_w, dt_proj_b, (float*)p_dt,
                                     CMROWS, CDMAMBA, CDMODEL);
    // 3) normalized B, C
    bc_kernel<<<CMROWS / 4, 128>>>(x_norm, B_proj_w, C_proj_w);
    // 4-6) chunked selective scan
    dim3 scan_grid(CDMAMBA / 256, CNCHUNK, CBATCH);
    scan_pass1<<<scan_grid, 256>>>(A_log);
    scan_pass2<<<CMROWS / CSEQ * CSEQ * 0 + (CBATCH * CDMAMBA) / 256, 256>>>(A_log);
    scan_pass3<<<scan_grid, 256>>>(A_log, Dvec);
    // 7) out = y @ out_proj_w^T
    sgemm_abt<0><<<gemm_grid, 256>>>((const float*)p_y, out_proj_w, nullptr, out,
                                     CMROWS, CDMAMBA, CDMAMBA);
}

// round 3
// speedup vs baseline: 2.1756x; 2.1756x over previous
#include <cuda_runtime.h>
#include <cuda_bf16.h>
#include <math.h>
#include <stdint.h>

#define CBATCH   4
#define CSEQ     2048
#define CDMODEL  1024
#define CDMAMBA  2048
#define CDSTATE  16
#define CNHEADS  32
#define CMROWS   (CBATCH * CSEQ)          // 8192
#define CNCHUNK  32
#define CLCHUNK  (CSEQ / CNCHUNK)         // 64
#define CHEADDIM (CDMAMBA / CNHEADS)      // 64

typedef unsigned short ushort_t;

// ---------------- scratch (static device arrays; no runtime allocation) ----------------
__device__ float g_xssm[CMROWS * CDMAMBA];
__device__ float g_dt  [CMROWS * CDMAMBA];
__device__ float g_Bn  [CMROWS * CDSTATE];
__device__ float g_Cn  [CMROWS * CDSTATE];
__device__ float g_hloc [CBATCH * CNCHUNK * CDSTATE * CDMAMBA];
__device__ float g_hinit[CBATCH * CNCHUNK * CDSTATE * CDMAMBA];
__device__ float g_S    [CBATCH * CNCHUNK * CDMAMBA];

// bf16 split operands
__device__ ushort_t g_xn_h[CMROWS * CDMODEL];
__device__ ushort_t g_xn_l[CMROWS * CDMODEL];
__device__ ushort_t g_w1_h[CDMAMBA * CDMODEL];
__device__ ushort_t g_w1_l[CDMAMBA * CDMODEL];
__device__ ushort_t g_w2_h[CDMAMBA * CDMODEL];
__device__ ushort_t g_w2_l[CDMAMBA * CDMODEL];
__device__ ushort_t g_w3_h[CDMAMBA * CDMAMBA];
__device__ ushort_t g_w3_l[CDMAMBA * CDMAMBA];
__device__ ushort_t g_y_h[CMROWS * CDMAMBA];
__device__ ushort_t g_y_l[CMROWS * CDMAMBA];

// ---------------- PTX helpers (baseline features only: sm_80-level) ----------------
__device__ __forceinline__ uint32_t smem_u32(const void* p) {
    uint32_t a;
    asm("{ .reg .u64 t; cvta.to.shared.u64 t, %1; cvt.u32.u64 %0, t; }" : "=r"(a) : "l"(p));
    return a;
}

#define CP_ASYNC16(dst, src) \
    asm volatile("cp.async.cg.shared.global [%0], [%1], 16;" :: "r"(dst), "l"(src))
#define CP_COMMIT() asm volatile("cp.async.commit_group;" ::: "memory")
#define CP_WAIT0() asm volatile("cp.async.wait_group 0;" ::: "memory")
#define CP_WAIT1() asm volatile("cp.async.wait_group 1;" ::: "memory")
#define CP_WAIT2() asm volatile("cp.async.wait_group 2;" ::: "memory")

#define LDSM4(r, addr) \
    asm volatile("ldmatrix.sync.aligned.m8n8.x4.shared.b16 {%0,%1,%2,%3}, [%4];" \
        : "=r"((r)[0]), "=r"((r)[1]), "=r"((r)[2]), "=r"((r)[3]) : "r"(addr))

#define MMA_BF16(d, a, b0, b1) \
    asm volatile("mma.sync.aligned.m16n8k16.row.col.f32.bf16.bf16.f32 " \
        "{%0,%1,%2,%3}, {%4,%5,%6,%7}, {%8,%9}, {%0,%1,%2,%3};" \
        : "+f"((d)[0]), "+f"((d)[1]), "+f"((d)[2]), "+f"((d)[3]) \
        : "r"((a)[0]), "r"((a)[1]), "r"((a)[2]), "r"((a)[3]), "r"(b0), "r"(b1))

__device__ __forceinline__ uint32_t swz(uint32_t off) {   // SW128 xor swizzle
    return off ^ ((off >> 3) & 0x70);
}

// ---------------- bf16 split conversion ----------------
__device__ __forceinline__ void split1(float v, ushort_t& h, ushort_t& l) {
    __nv_bfloat16 bh = __float2bfloat16(v);
    h = __bfloat16_as_ushort(bh);
    l = __bfloat16_as_ushort(__float2bfloat16(v - __bfloat162float(bh)));
}

__global__ __launch_bounds__(256) void conv_split(const float* __restrict__ in,
                                                  ushort_t* __restrict__ hi,
                                                  ushort_t* __restrict__ lo,
                                                  int n4) {
    int i = blockIdx.x * 256 + threadIdx.x;
    if (i >= n4) return;
    float4 v = reinterpret_cast<const float4*>(in)[i];
    ushort4 h, l;
    split1(v.x, h.x, l.x);
    split1(v.y, h.y, l.y);
    split1(v.z, h.z, l.z);
    split1(v.w, h.w, l.w);
    reinterpret_cast<ushort4*>(hi)[i] = h;
    reinterpret_cast<ushort4*>(lo)[i] = l;
}

__device__ __forceinline__ float dt_transform(float v, float b) {
    v += b;
    v = fminf(fmaxf(v, -10.0f), 5.0f);
    v = log1pf(expf(v));
    return fminf(fmaxf(v, 1e-4f), 0.1f);
}

// ---------------- HMMA split-bf16 GEMM ----------------
// C[m,n] = sum_k A[m,k]*W[n,k]; tile 128x128, BK=64, 3-stage cp.async pipeline.
// Per stage: Ah,Al (128x64 bf16, 16KB each), Wh,Wl (128x64, 16KB each) = 64KB.
#define TILE_B   16384
#define STAGE_B  65536
#define NSTAGE   3
#define SM_TOTAL (NSTAGE * STAGE_B)   // 196608

__device__ __forceinline__ void stage_load(
    const ushort_t* __restrict__ Ah, const ushort_t* __restrict__ Al,
    const ushort_t* __restrict__ Wh, const ushort_t* __restrict__ Wl,
    uint32_t sbase, int m0, int n0, int kc, int K, int tid) {
#pragma unroll
    for (int tile = 0; tile < 4; tile++) {
        const ushort_t* g = (tile == 0) ? Ah : (tile == 1) ? Al : (tile == 2) ? Wh : Wl;
        int row0 = (tile < 2) ? m0 : n0;
#pragma unroll
        for (int j = 0; j < 4; j++) {
            int idx = tid + j * 256;           // 0..1023
            int row = idx >> 3, seg = idx & 7;
            const ushort_t* src = g + (size_t)(row0 + row) * K + kc + seg * 8;
            uint32_t dst = sbase + tile * TILE_B + swz((uint32_t)(row * 128 + seg * 16));
            CP_ASYNC16(dst, src);
        }
    }
}

__device__ __forceinline__ void stage_compute(uint32_t sbase, int wm, int wn,
                                              int lane, float acc[2][8][4]) {
    const uint32_t aAh = sbase;
    const uint32_t aAl = sbase + TILE_B;
    const uint32_t aWh = sbase + 2 * TILE_B;
    const uint32_t aWl = sbase + 3 * TILE_B;
    const int arow = wm + (lane & 15);
    const int akb  = (lane >> 4) * 16;                       // k-seg byte offset
    const int brow = wn + ((lane >> 4) << 3) + (lane & 7);
    const int bkb  = ((lane >> 3) & 1) * 16;

#pragma unroll
    for (int ks = 0; ks < 4; ks++) {
        const int kb = ks * 32;                              // bytes per k16
        uint32_t ah[2][4], al[2][4];
#pragma unroll
        for (int mi = 0; mi < 2; mi++) {
            uint32_t off = swz((uint32_t)((arow + mi * 16) * 128 + akb + kb));
            LDSM4(ah[mi], aAh + off);
            LDSM4(al[mi], aAl + off);
        }
        uint32_t bh[4][4], bl[4][4];
#pragma unroll
        for (int ni = 0; ni < 4; ni++) {
            uint32_t off = swz((uint32_t)((brow + ni * 16) * 128 + bkb + kb));
            LDSM4(bh[ni], aWh + off);
            LDSM4(bl[ni], aWl + off);
        }
#pragma unroll
        for (int mi = 0; mi < 2; mi++) {
#pragma unroll
            for (int ni = 0; ni < 4; ni++) {
                MMA_BF16(acc[mi][2 * ni + 0], ah[mi], bh[ni][0], bh[ni][1]);
                MMA_BF16(acc[mi][2 * ni + 0], ah[mi], bl[ni][0], bl[ni][1]);
                MMA_BF16(acc[mi][2 * ni + 0], al[mi], bh[ni][0], bh[ni][1]);
                MMA_BF16(acc[mi][2 * ni + 1], ah[mi], bh[ni][2], bh[ni][3]);
                MMA_BF16(acc[mi][2 * ni + 1], ah[mi], bl[ni][2], bl[ni][3]);
                MMA_BF16(acc[mi][2 * ni + 1], al[mi], bh[ni][2], bh[ni][3]);
            }
        }
    }
}

template <int EPI>
__global__ __launch_bounds__(256, 1) void gemm_mma(
    const ushort_t* __restrict__ Ah, const ushort_t* __restrict__ Al,
    const ushort_t* __restrict__ Wh, const ushort_t* __restrict__ Wl,
    const float* __restrict__ bias, float* __restrict__ C, int M, int N, int K) {
    extern __shared__ __align__(1024) char smem[];
    const uint32_t sb = smem_u32(smem);
    const int tid = threadIdx.x, lane = tid & 31, w = tid >> 5;
    const int m0 = blockIdx.y * 128, n0 = blockIdx.x * 128;
    const int wm = (w & 3) * 32, wn = (w >> 2) * 64;
    const int NC = K >> 6;

    float acc[2][8][4];
#pragma unroll
    for (int i = 0; i < 2; i++)
#pragma unroll
        for (int j = 0; j < 8; j++)
#pragma unroll
            for (int q = 0; q < 4; q++) acc[i][j][q] = 0.0f;

    stage_load(Ah, Al, Wh, Wl, sb + 0 * STAGE_B, m0, n0, 0, K, tid);  CP_COMMIT();
    stage_load(Ah, Al, Wh, Wl, sb + 1 * STAGE_B, m0, n0, 64, K, tid); CP_COMMIT();
    stage_load(Ah, Al, Wh, Wl, sb + 2 * STAGE_B, m0, n0, 128, K, tid); CP_COMMIT();

    int sidx = 0;
    for (int c = 0; c < NC; c++) {
        const int rem = NC - 1 - c;
        if (rem >= 2) { CP_WAIT2(); } else if (rem == 1) { CP_WAIT1(); } else { CP_WAIT0(); }
        __syncthreads();
        const uint32_t stage = sb + sidx * STAGE_B;
        stage_compute(stage, wm, wn, lane, acc);
        __syncthreads();
        if (c + 3 < NC) {
            stage_load(Ah, Al, Wh, Wl, stage, m0, n0, (c + 3) * 64, K, tid);
            CP_COMMIT();
        }
        sidx = (sidx == 2) ? 0 : sidx + 1;
    }

    // epilogue
    const int gm = m0 + wm, gn = n0 + wn;
    const int r = lane >> 2, cp = (lane & 3) * 2;
#pragma unroll
    for (int mi = 0; mi < 2; mi++) {
#pragma unroll
        for (int nj = 0; nj < 8; nj++) {
            int row = gm + mi * 16 + r;
            int col = gn + nj * 8 + cp;
            float v0 = acc[mi][nj][0], v1 = acc[mi][nj][1];
            float v2 = acc[mi][nj][2], v3 = acc[mi][nj][3];
            if (EPI == 1) {
                float2 bb = *reinterpret_cast<const float2*>(&bias[col]);
                v0 = dt_transform(v0, bb.x);
                v1 = dt_transform(v1, bb.y);
                v2 = dt_transform(v2, bb.x);
                v3 = dt_transform(v3, bb.y);
            }
            *reinterpret_cast<float2*>(&C[(size_t)row * N + col]) = make_float2(v0, v1);
            *reinterpret_cast<float2*>(&C[(size_t)(row + 8) * N + col]) = make_float2(v2, v3);
        }
    }
}

// ---------------- B/C projection + row normalization ----------------
__global__ __launch_bounds__(128) void bc_kernel(const float* __restrict__ X,
                                                 const float* __restrict__ WB,
                                                 const float* __restrict__ WC) {
    int warp = threadIdx.x >> 5;
    int lane = threadIdx.x & 31;
    int m = blockIdx.x * 4 + warp;
    const float* Wr = (lane < 16) ? (WB + (size_t)lane * CDMODEL)
                                  : (WC + (size_t)(lane - 16) * CDMODEL);
    const float* Xr = X + (size_t)m * CDMODEL;

    float4 av = make_float4(0.f, 0.f, 0.f, 0.f);
    for (int k = 0; k < CDMODEL; k += 4) {
        float4 xv = *reinterpret_cast<const float4*>(&Xr[k]);
        float4 wv = *reinterpret_cast<const float4*>(&Wr[k]);
        av.x = fmaf(xv.x, wv.x, av.x);
        av.y = fmaf(xv.y, wv.y, av.y);
        av.z = fmaf(xv.z, wv.z, av.z);
        av.w = fmaf(xv.w, wv.w, av.w);
    }
    float acc = (av.x + av.y) + (av.z + av.w);

    float ss = acc * acc;
#pragma unroll
    for (int off = 8; off >= 1; off >>= 1)
        ss += __shfl_xor_sync(0xffffffffu, ss, off);
    float scale = 1.0f / fmaxf(sqrtf(ss), 1.0f);
    float v = acc * scale;
    if (lane < 16) g_Bn[(size_t)m * 16 + lane] = v;
    else           g_Cn[(size_t)m * 16 + (lane - 16)] = v;
}

__device__ __forceinline__ void load16(const float* p, float* v) {
    const float4* q = reinterpret_cast<const float4*>(p);
    float4 a = q[0], b = q[1], c = q[2], d = q[3];
    v[0] = a.x; v[1] = a.y; v[2] = a.z; v[3] = a.w;
    v[4] = b.x; v[5] = b.y; v[6] = b.z; v[7] = b.w;
    v[8] = c.x; v[9] = c.y; v[10] = c.z; v[11] = c.w;
    v[12] = d.x; v[13] = d.y; v[14] = d.z; v[15] = d.w;
}

__device__ __forceinline__ bool load_A(const float* __restrict__ A_log, int d, float* Av) {
    int head = d / CHEADDIM;
    bool fast = true;
#pragma unroll
    for (int n = 0; n < 16; n++) {
        Av[n] = expf(A_log[head * 16 + n]);
        if (fabsf(Av[n] - (float)(n + 1)) > 1e-3f * (float)(n + 1)) fast = false;
    }
    return fast;
}

// ---------------- scan pass 1 ----------------
__global__ __launch_bounds__(256) void scan_pass1(const float* __restrict__ A_log) {
    int d = blockIdx.x * 256 + threadIdx.x;
    int c = blockIdx.y;
    int b = blockIdx.z;

    float Av[16];
    bool fastA = load_A(A_log, d, Av);

    float h[16];
#pragma unroll
    for (int n = 0; n < 16; n++) h[n] = 0.0f;
    float S = 0.0f;

    int row0 = b * CSEQ + c * CLCHUNK;
    for (int t = 0; t < CLCHUNK; t++) {
        size_t ro = (size_t)(row0 + t) * CDMAMBA + d;
        float dt = g_dt[ro];
        float x  = g_xssm[ro];
        float Bv[16];
        load16(g_Bn + (size_t)(row0 + t) * 16, Bv);
        S += dt;
        float dtx = dt * x;
        if (fastA) {
            float r = __expf(-dt), p = 1.0f;
#pragma unroll
            for (int n = 0; n < 16; n++) { p *= r; h[n] = fmaf(p, h[n], dtx * Bv[n]); }
        } else {
#pragma unroll
            for (int n = 0; n < 16; n++) {
                float dec = __expf(-dt * Av[n]);
                h[n] = fmaf(dec, h[n], dtx * Bv[n]);
            }
        }
    }
    size_t base = ((size_t)(b * CNCHUNK + c) * 16) * CDMAMBA + d;
#pragma unroll
    for (int n = 0; n < 16; n++) g_hloc[base + (size_t)n * CDMAMBA] = h[n];
    g_S[(size_t)(b * CNCHUNK + c) * CDMAMBA + d] = S;
}

// ---------------- scan pass 2 ----------------
__global__ __launch_bounds__(256) void scan_pass2(const float* __restrict__ A_log) {
    int idx = blockIdx.x * 256 + threadIdx.x;
    int b = idx / CDMAMBA;
    int d = idx % CDMAMBA;

    float Av[16];
    bool fastA = load_A(A_log, d, Av);

    float h[16];
#pragma unroll
    for (int n = 0; n < 16; n++) h[n] = 0.0f;

    for (int c = 0; c < CNCHUNK; c++) {
        size_t base = ((size_t)(b * CNCHUNK + c) * 16) * CDMAMBA + d;
#pragma unroll
        for (int n = 0; n < 16; n++) g_hinit[base + (size_t)n * CDMAMBA] = h[n];
        float S = g_S[(size_t)(b * CNCHUNK + c) * CDMAMBA + d];
        if (fastA) {
            float R = __expf(-S), p = 1.0f;
#pragma unroll
            for (int n = 0; n < 16; n++) {
                p *= R;
                h[n] = fmaf(p, h[n], g_hloc[base + (size_t)n * CDMAMBA]);
            }
        } else {
#pragma unroll
            for (int n = 0; n < 16; n++) {
                float P = __expf(-S * Av[n]);
                h[n] = fmaf(P, h[n], g_hloc[base + (size_t)n * CDMAMBA]);
            }
        }
    }
}

// ---------------- scan pass 3: emit y as bf16 split ----------------
__global__ __launch_bounds__(256) void scan_pass3(const float* __restrict__ A_log,
                                                  const float* __restrict__ Dvec) {
    int d = blockIdx.x * 256 + threadIdx.x;
    int c = blockIdx.y;
    int b = blockIdx.z;

    float Av[16];
    bool fastA = load_A(A_log, d, Av);
    float Dd = Dvec[d];

    float h[16];
    size_t base = ((size_t)(b * CNCHUNK + c) * 16) * CDMAMBA + d;
#pragma unroll
    for (int n = 0; n < 16; n++) h[n] = g_hinit[base + (size_t)n * CDMAMBA];

    int row0 = b * CSEQ + c * CLCHUNK;
    for (int t = 0; t < CLCHUNK; t++) {
        size_t ro = (size_t)(row0 + t) * CDMAMBA + d;
        float dt = g_dt[ro];
        float x  = g_xssm[ro];
        float Bv[16], Cv[16];
        load16(g_Bn + (size_t)(row0 + t) * 16, Bv);
        load16(g_Cn + (size_t)(row0 + t) * 16, Cv);
        float dtx = dt * x;
        float y = 0.0f;
        if (fastA) {
            float r = __expf(-dt), p = 1.0f;
#pragma unroll
            for (int n = 0; n < 16; n++) {
                p *= r;
                h[n] = fmaf(p, h[n], dtx * Bv[n]);
                y = fmaf(h[n], Cv[n], y);
            }
        } else {
#pragma unroll
            for (int n = 0; n < 16; n++) {
                float dec = __expf(-dt * Av[n]);
                h[n] = fmaf(dec, h[n], dtx * Bv[n]);
                y = fmaf(h[n], Cv[n], y);
            }
        }
        float yv = fmaf(x, Dd, y);
        ushort_t yh, yl;
        split1(yv, yh, yl);
        g_y_h[ro] = yh;
        g_y_l[ro] = yl;
    }
}

// ---------------- launch ----------------
extern "C" void kernel_launch(void* const* d_in, const int* in_sizes, int n_in,
                              void* d_out, int out_size) {
    (void)in_sizes; (void)n_in; (void)out_size;
    const float* x_norm     = (const float*)d_in[0];
    const float* x_proj_w   = (const float*)d_in[1];
    const float* dt_proj_w  = (const float*)d_in[2];
    const float* dt_proj_b  = (const float*)d_in[3];
    const float* B_proj_w   = (const float*)d_in[4];
    const float* C_proj_w   = (const float*)d_in[5];
    const float* A_log      = (const float*)d_in[6];
    const float* Dvec       = (const float*)d_in[7];
    const float* out_proj_w = (const float*)d_in[8];
    float* out = (float*)d_out;

    void *p_xssm, *p_dt;
    void *p_xnh, *p_xnl, *p_w1h, *p_w1l, *p_w2h, *p_w2l, *p_w3h, *p_w3l, *p_yh, *p_yl;
    cudaGetSymbolAddress(&p_xssm, g_xssm);
    cudaGetSymbolAddress(&p_dt, g_dt);
    cudaGetSymbolAddress(&p_xnh, g_xn_h);  cudaGetSymbolAddress(&p_xnl, g_xn_l);
    cudaGetSymbolAddress(&p_w1h, g_w1_h);  cudaGetSymbolAddress(&p_w1l, g_w1_l);
    cudaGetSymbolAddress(&p_w2h, g_w2_h);  cudaGetSymbolAddress(&p_w2l, g_w2_l);
    cudaGetSymbolAddress(&p_w3h, g_w3_h);  cudaGetSymbolAddress(&p_w3l, g_w3_l);
    cudaGetSymbolAddress(&p_yh, g_y_h);    cudaGetSymbolAddress(&p_yl, g_y_l);

    cudaFuncSetAttribute(gemm_mma<0>, cudaFuncAttributeMaxDynamicSharedMemorySize, SM_TOTAL);
    cudaFuncSetAttribute(gemm_mma<1>, cudaFuncAttributeMaxDynamicSharedMemorySize, SM_TOTAL);

    // bf16 splits of x_norm and the three GEMM weights
    {
        int n4 = (CMROWS * CDMODEL) / 4;
        conv_split<<<n4 / 256, 256>>>(x_norm, (ushort_t*)p_xnh, (ushort_t*)p_xnl, n4);
        n4 = (CDMAMBA * CDMODEL) / 4;
        conv_split<<<n4 / 256, 256>>>(x_proj_w, (ushort_t*)p_w1h, (ushort_t*)p_w1l, n4);
        conv_split<<<n4 / 256, 256>>>(dt_proj_w, (ushort_t*)p_w2h, (ushort_t*)p_w2l, n4);
        n4 = (CDMAMBA * CDMAMBA) / 4;
        conv_split<<<n4 / 256, 256>>>(out_proj_w, (ushort_t*)p_w3h, (ushort_t*)p_w3l, n4);
    }

    dim3 gemm_grid(CDMAMBA / 128, CMROWS / 128);   // (16, 64)

    // 1) x_ssm = x_norm @ x_proj_w^T
    gemm_mma<0><<<gemm_grid, 256, SM_TOTAL>>>(
        (const ushort_t*)p_xnh, (const ushort_t*)p_xnl,
        (const ushort_t*)p_w1h, (const ushort_t*)p_w1l,
        nullptr, (float*)p_xssm, CMROWS, CDMAMBA, CDMODEL);
    // 2) dt = clip(softplus(clip(x_norm @ dt_proj_w^T + b)))
    gemm_mma<1><<<gemm_grid, 256, SM_TOTAL>>>(
        (const ushort_t*)p_xnh, (const ushort_t*)p_xnl,
        (const ushort_t*)p_w2h, (const ushort_t*)p_w2l,
        dt_proj_b, (float*)p_dt, CMROWS, CDMAMBA, CDMODEL);
    // 3) normalized B, C
    bc_kernel<<<CMROWS / 4, 128>>>(x_norm, B_proj_w, C_proj_w);
    // 4-6) chunked selective scan (pass3 emits y split into bf16 hi/lo)
    dim3 scan_grid(CDMAMBA / 256, CNCHUNK, CBATCH);
    scan_pass1<<<scan_grid, 256>>>(A_log);
    scan_pass2<<<(CBATCH * CDMAMBA) / 256, 256>>>(A_log);
    scan_pass3<<<scan_grid, 256>>>(A_log, Dvec);
    // 7) out = y @ out_proj_w^T
    gemm_mma<0><<<gemm_grid, 256, SM_TOTAL>>>(
        (const ushort_t*)p_yh, (const ushort_t*)p_yl,
        (const ushort_t*)p_w3h, (const ushort_t*)p_w3l,
        nullptr, out, CMROWS, CDMAMBA, CDMAMBA);
}

// round 4
// speedup vs baseline: 2.7798x; 1.2777x over previous
#include <cuda_runtime.h>
#include <cuda_fp16.h>
#include <math.h>
#include <stdint.h>

#define CBATCH   4
#define CSEQ     2048
#define CDMODEL  1024
#define CDMAMBA  2048
#define CDSTATE  16
#define CNHEADS  32
#define CMROWS   (CBATCH * CSEQ)          // 8192
#define CNCHUNK  32
#define CLCHUNK  (CSEQ / CNCHUNK)         // 64
#define CHEADDIM (CDMAMBA / CNHEADS)      // 64

typedef unsigned short ushort_t;

// ---------------- scratch (static device arrays; no runtime allocation) ----------------
__device__ float g_xssm[CMROWS * CDMAMBA];
__device__ float g_dt  [CMROWS * CDMAMBA];
__device__ float g_Bn  [CMROWS * CDSTATE];
__device__ float g_Cn  [CMROWS * CDSTATE];
__device__ float g_hloc [CBATCH * CNCHUNK * CDSTATE * CDMAMBA];
__device__ float g_hinit[CBATCH * CNCHUNK * CDSTATE * CDMAMBA];
__device__ float g_S    [CBATCH * CNCHUNK * CDMAMBA];

// fp16 split operands: A-side needs hi+lo, W-side hi only
__device__ ushort_t g_xn_h[CMROWS * CDMODEL];
__device__ ushort_t g_xn_l[CMROWS * CDMODEL];
__device__ ushort_t g_w1_h[CDMAMBA * CDMODEL];
__device__ ushort_t g_w2_h[CDMAMBA * CDMODEL];
__device__ ushort_t g_w3_h[CDMAMBA * CDMAMBA];
__device__ ushort_t g_y_h[CMROWS * CDMAMBA];
__device__ ushort_t g_y_l[CMROWS * CDMAMBA];

// ---------------- PTX helpers (baseline sm_80-level features only) ----------------
__device__ __forceinline__ uint32_t smem_u32(const void* p) {
    uint32_t a;
    asm("{ .reg .u64 t; cvta.to.shared.u64 t, %1; cvt.u32.u64 %0, t; }" : "=r"(a) : "l"(p));
    return a;
}

#define CP_ASYNC16(dst, src) \
    asm volatile("cp.async.cg.shared.global [%0], [%1], 16;" :: "r"(dst), "l"(src))
#define CP_COMMIT() asm volatile("cp.async.commit_group;" ::: "memory")
#define CP_WAIT0() asm volatile("cp.async.wait_group 0;" ::: "memory")
#define CP_WAIT1() asm volatile("cp.async.wait_group 1;" ::: "memory")

#define LDSM4(r, addr) \
    asm volatile("ldmatrix.sync.aligned.m8n8.x4.shared.b16 {%0,%1,%2,%3}, [%4];" \
        : "=r"((r)[0]), "=r"((r)[1]), "=r"((r)[2]), "=r"((r)[3]) : "r"(addr))

#define MMA_F16(d, a, b0, b1) \
    asm volatile("mma.sync.aligned.m16n8k16.row.col.f32.f16.f16.f32 " \
        "{%0,%1,%2,%3}, {%4,%5,%6,%7}, {%8,%9}, {%0,%1,%2,%3};" \
        : "+f"((d)[0]), "+f"((d)[1]), "+f"((d)[2]), "+f"((d)[3]) \
        : "r"((a)[0]), "r"((a)[1]), "r"((a)[2]), "r"((a)[3]), "r"(b0), "r"(b1))

__device__ __forceinline__ uint32_t swz(uint32_t off) {   // SW128 xor swizzle
    return off ^ ((off >> 3) & 0x70);
}

// ---------------- fp16 split conversion ----------------
__device__ __forceinline__ void split1(float v, ushort_t& h, ushort_t& l) {
    __half hh = __float2half(v);
    h = __half_as_ushort(hh);
    l = __half_as_ushort(__float2half(v - __half2float(hh)));
}

__global__ __launch_bounds__(256) void conv_split(const float* __restrict__ in,
                                                  ushort_t* __restrict__ hi,
                                                  ushort_t* __restrict__ lo,
                                                  int n4) {
    int i = blockIdx.x * 256 + threadIdx.x;
    if (i >= n4) return;
    float4 v = reinterpret_cast<const float4*>(in)[i];
    ushort4 h, l;
    split1(v.x, h.x, l.x);
    split1(v.y, h.y, l.y);
    split1(v.z, h.z, l.z);
    split1(v.w, h.w, l.w);
    reinterpret_cast<ushort4*>(hi)[i] = h;
    reinterpret_cast<ushort4*>(lo)[i] = l;
}

__global__ __launch_bounds__(256) void conv_h(const float* __restrict__ in,
                                              ushort_t* __restrict__ hi, int n4) {
    int i = blockIdx.x * 256 + threadIdx.x;
    if (i >= n4) return;
    float4 v = reinterpret_cast<const float4*>(in)[i];
    ushort4 h;
    h.x = __half_as_ushort(__float2half(v.x));
    h.y = __half_as_ushort(__float2half(v.y));
    h.z = __half_as_ushort(__float2half(v.z));
    h.w = __half_as_ushort(__float2half(v.w));
    reinterpret_cast<ushort4*>(hi)[i] = h;
}

__device__ __forceinline__ float dt_transform(float v, float b) {
    v += b;
    v = fminf(fmaxf(v, -10.0f), 5.0f);
    v = log1pf(expf(v));
    return fminf(fmaxf(v, 1e-4f), 0.1f);
}

// ---------------- HMMA fp16x2 GEMM ----------------
// C[m,n] = sum_k A[m,k]*W[n,k] ~= (Ah+Al)[m,:]*Wh[n,:]; tile 128x128, BK=64,
// 2-stage cp.async pipeline, 3 operand tiles of 16KB -> 48KB/stage, 96KB/CTA, 2 CTA/SM.
#define TILE_B   16384
#define STAGE_B  49152
#define SM_TOTAL (2 * STAGE_B)   // 98304

__device__ __forceinline__ void stage_load(
    const ushort_t* __restrict__ Ah, const ushort_t* __restrict__ Al,
    const ushort_t* __restrict__ Wh,
    uint32_t sbase, int m0, int n0, int kc, int K, int tid) {
#pragma unroll
    for (int tile = 0; tile < 3; tile++) {
        const ushort_t* g = (tile == 0) ? Ah : (tile == 1) ? Al : Wh;
        int row0 = (tile < 2) ? m0 : n0;
#pragma unroll
        for (int j = 0; j < 4; j++) {
            int idx = tid + j * 256;           // 0..1023
            int row = idx >> 3, seg = idx & 7;
            const ushort_t* src = g + (size_t)(row0 + row) * K + kc + seg * 8;
            uint32_t dst = sbase + tile * TILE_B + swz((uint32_t)(row * 128 + seg * 16));
            CP_ASYNC16(dst, src);
        }
    }
}

__device__ __forceinline__ void stage_compute(uint32_t sbase, int wm, int wn,
                                              int lane, float acc[2][8][4]) {
    const uint32_t aAh = sbase;
    const uint32_t aAl = sbase + TILE_B;
    const uint32_t aWh = sbase + 2 * TILE_B;
    const int arow = wm + (lane & 15);
    const int akb  = (lane >> 4) * 16;
    const int brow = wn + ((lane >> 4) << 3) + (lane & 7);
    const int bkb  = ((lane >> 3) & 1) * 16;

#pragma unroll
    for (int ks = 0; ks < 4; ks++) {
        const int kb = ks * 32;
        uint32_t ah[2][4], al[2][4];
#pragma unroll
        for (int mi = 0; mi < 2; mi++) {
            uint32_t off = swz((uint32_t)((arow + mi * 16) * 128 + akb + kb));
            LDSM4(ah[mi], aAh + off);
            LDSM4(al[mi], aAl + off);
        }
        uint32_t bh[4][4];
#pragma unroll
        for (int ni = 0; ni < 4; ni++) {
            uint32_t off = swz((uint32_t)((brow + ni * 16) * 128 + bkb + kb));
            LDSM4(bh[ni], aWh + off);
        }
#pragma unroll
        for (int mi = 0; mi < 2; mi++) {
#pragma unroll
            for (int ni = 0; ni < 4; ni++) {
                MMA_F16(acc[mi][2 * ni + 0], ah[mi], bh[ni][0], bh[ni][1]);
                MMA_F16(acc[mi][2 * ni + 0], al[mi], bh[ni][0], bh[ni][1]);
                MMA_F16(acc[mi][2 * ni + 1], ah[mi], bh[ni][2], bh[ni][3]);
                MMA_F16(acc[mi][2 * ni + 1], al[mi], bh[ni][2], bh[ni][3]);
            }
        }
    }
}

template <int EPI>
__global__ __launch_bounds__(256, 2) void gemm_mma(
    const ushort_t* __restrict__ Ah, const ushort_t* __restrict__ Al,
    const ushort_t* __restrict__ Wh,
    const float* __restrict__ bias, float* __restrict__ C, int M, int N, int K) {
    extern __shared__ __align__(1024) char smem[];
    const uint32_t sb = smem_u32(smem);
    const int tid = threadIdx.x, lane = tid & 31, w = tid >> 5;
    const int m0 = blockIdx.y * 128, n0 = blockIdx.x * 128;
    const int wm = (w & 3) * 32, wn = (w >> 2) * 64;
    const int NC = K >> 6;

    float acc[2][8][4];
#pragma unroll
    for (int i = 0; i < 2; i++)
#pragma unroll
        for (int j = 0; j < 8; j++)
#pragma unroll
            for (int q = 0; q < 4; q++) acc[i][j][q] = 0.0f;

    stage_load(Ah, Al, Wh, sb + 0 * STAGE_B, m0, n0, 0, K, tid);  CP_COMMIT();
    stage_load(Ah, Al, Wh, sb + 1 * STAGE_B, m0, n0, 64, K, tid); CP_COMMIT();

    for (int c = 0; c < NC; c++) {
        if (c + 1 < NC) { CP_WAIT1(); } else { CP_WAIT0(); }
        __syncthreads();
        const uint32_t stage = sb + (c & 1) * STAGE_B;
        stage_compute(stage, wm, wn, lane, acc);
        __syncthreads();
        if (c + 2 < NC) {
            stage_load(Ah, Al, Wh, stage, m0, n0, (c + 2) * 64, K, tid);
            CP_COMMIT();
        }
    }

    // epilogue
    const int gm = m0 + wm, gn = n0 + wn;
    const int r = lane >> 2, cp = (lane & 3) * 2;
#pragma unroll
    for (int mi = 0; mi < 2; mi++) {
#pragma unroll
        for (int nj = 0; nj < 8; nj++) {
            int row = gm + mi * 16 + r;
            int col = gn + nj * 8 + cp;
            float v0 = acc[mi][nj][0], v1 = acc[mi][nj][1];
            float v2 = acc[mi][nj][2], v3 = acc[mi][nj][3];
            if (EPI == 1) {
                float2 bb = *reinterpret_cast<const float2*>(&bias[col]);
                v0 = dt_transform(v0, bb.x);
                v1 = dt_transform(v1, bb.y);
                v2 = dt_transform(v2, bb.x);
                v3 = dt_transform(v3, bb.y);
            }
            *reinterpret_cast<float2*>(&C[(size_t)row * N + col]) = make_float2(v0, v1);
            *reinterpret_cast<float2*>(&C[(size_t)(row + 8) * N + col]) = make_float2(v2, v3);
        }
    }
}

// ---------------- B/C projection + row normalization ----------------
__global__ __launch_bounds__(128) void bc_kernel(const float* __restrict__ X,
                                                 const float* __restrict__ WB,
                                                 const float* __restrict__ WC) {
    int warp = threadIdx.x >> 5;
    int lane = threadIdx.x & 31;
    int m = blockIdx.x * 4 + warp;
    const float* Wr = (lane < 16) ? (WB + (size_t)lane * CDMODEL)
                                  : (WC + (size_t)(lane - 16) * CDMODEL);
    const float* Xr = X + (size_t)m * CDMODEL;

    float4 av = make_float4(0.f, 0.f, 0.f, 0.f);
    for (int k = 0; k < CDMODEL; k += 4) {
        float4 xv = *reinterpret_cast<const float4*>(&Xr[k]);
        float4 wv = *reinterpret_cast<const float4*>(&Wr[k]);
        av.x = fmaf(xv.x, wv.x, av.x);
        av.y = fmaf(xv.y, wv.y, av.y);
        av.z = fmaf(xv.z, wv.z, av.z);
        av.w = fmaf(xv.w, wv.w, av.w);
    }
    float acc = (av.x + av.y) + (av.z + av.w);

    float ss = acc * acc;
#pragma unroll
    for (int off = 8; off >= 1; off >>= 1)
        ss += __shfl_xor_sync(0xffffffffu, ss, off);
    float scale = 1.0f / fmaxf(sqrtf(ss), 1.0f);
    float v = acc * scale;
    if (lane < 16) g_Bn[(size_t)m * 16 + lane] = v;
    else           g_Cn[(size_t)m * 16 + (lane - 16)] = v;
}

__device__ __forceinline__ void load16(const float* p, float* v) {
    const float4* q = reinterpret_cast<const float4*>(p);
    float4 a = q[0], b = q[1], c = q[2], d = q[3];
    v[0] = a.x; v[1] = a.y; v[2] = a.z; v[3] = a.w;
    v[4] = b.x; v[5] = b.y; v[6] = b.z; v[7] = b.w;
    v[8] = c.x; v[9] = c.y; v[10] = c.z; v[11] = c.w;
    v[12] = d.x; v[13] = d.y; v[14] = d.z; v[15] = d.w;
}

__device__ __forceinline__ bool load_A(const float* __restrict__ A_log, int d, float* Av) {
    int head = d / CHEADDIM;
    bool fast = true;
#pragma unroll
    for (int n = 0; n < 16; n++) {
        Av[n] = expf(A_log[head * 16 + n]);
        if (fabsf(Av[n] - (float)(n + 1)) > 1e-3f * (float)(n + 1)) fast = false;
    }
    return fast;
}

// ---------------- scan pass 1 ----------------
__global__ __launch_bounds__(256) void scan_pass1(const float* __restrict__ A_log) {
    int d = blockIdx.x * 256 + threadIdx.x;
    int c = blockIdx.y;
    int b = blockIdx.z;

    float Av[16];
    bool fastA = load_A(A_log, d, Av);

    float h[16];
#pragma unroll
    for (int n = 0; n < 16; n++) h[n] = 0.0f;
    float S = 0.0f;

    int row0 = b * CSEQ + c * CLCHUNK;
    for (int t = 0; t < CLCHUNK; t++) {
        size_t ro = (size_t)(row0 + t) * CDMAMBA + d;
        float dt = g_dt[ro];
        float x  = g_xssm[ro];
        float Bv[16];
        load16(g_Bn + (size_t)(row0 + t) * 16, Bv);
        S += dt;
        float dtx = dt * x;
        if (fastA) {
            float r = __expf(-dt), p = 1.0f;
#pragma unroll
            for (int n = 0; n < 16; n++) { p *= r; h[n] = fmaf(p, h[n], dtx * Bv[n]); }
        } else {
#pragma unroll
            for (int n = 0; n < 16; n++) {
                float dec = __expf(-dt * Av[n]);
                h[n] = fmaf(dec, h[n], dtx * Bv[n]);
            }
        }
    }
    size_t base = ((size_t)(b * CNCHUNK + c) * 16) * CDMAMBA + d;
#pragma unroll
    for (int n = 0; n < 16; n++) g_hloc[base + (size_t)n * CDMAMBA] = h[n];
    g_S[(size_t)(b * CNCHUNK + c) * CDMAMBA + d] = S;
}

// ---------------- scan pass 2 ----------------
__global__ __launch_bounds__(256) void scan_pass2(const float* __restrict__ A_log) {
    int idx = blockIdx.x * 256 + threadIdx.x;
    int b = idx / CDMAMBA;
    int d = idx % CDMAMBA;

    float Av[16];
    bool fastA = load_A(A_log, d, Av);

    float h[16];
#pragma unroll
    for (int n = 0; n < 16; n++) h[n] = 0.0f;

    for (int c = 0; c < CNCHUNK; c++) {
        size_t base = ((size_t)(b * CNCHUNK + c) * 16) * CDMAMBA + d;
#pragma unroll
        for (int n = 0; n < 16; n++) g_hinit[base + (size_t)n * CDMAMBA] = h[n];
        float S = g_S[(size_t)(b * CNCHUNK + c) * CDMAMBA + d];
        if (fastA) {
            float R = __expf(-S), p = 1.0f;
#pragma unroll
            for (int n = 0; n < 16; n++) {
                p *= R;
                h[n] = fmaf(p, h[n], g_hloc[base + (size_t)n * CDMAMBA]);
            }
        } else {
#pragma unroll
            for (int n = 0; n < 16; n++) {
                float P = __expf(-S * Av[n]);
                h[n] = fmaf(P, h[n], g_hloc[base + (size_t)n * CDMAMBA]);
            }
        }
    }
}

// ---------------- scan pass 3: emit y as fp16 split ----------------
__global__ __launch_bounds__(256) void scan_pass3(const float* __restrict__ A_log,
                                                  const float* __restrict__ Dvec) {
    int d = blockIdx.x * 256 + threadIdx.x;
    int c = blockIdx.y;
    int b = blockIdx.z;

    float Av[16];
    bool fastA = load_A(A_log, d, Av);
    float Dd = Dvec[d];

    float h[16];
    size_t base = ((size_t)(b * CNCHUNK + c) * 16) * CDMAMBA + d;
#pragma unroll
    for (int n = 0; n < 16; n++) h[n] = g_hinit[base + (size_t)n * CDMAMBA];

    int row0 = b * CSEQ + c * CLCHUNK;
    for (int t = 0; t < CLCHUNK; t++) {
        size_t ro = (size_t)(row0 + t) * CDMAMBA + d;
        float dt = g_dt[ro];
        float x  = g_xssm[ro];
        float Bv[16], Cv[16];
        load16(g_Bn + (size_t)(row0 + t) * 16, Bv);
        load16(g_Cn + (size_t)(row0 + t) * 16, Cv);
        float dtx = dt * x;
        float y = 0.0f;
        if (fastA) {
            float r = __expf(-dt), p = 1.0f;
#pragma unroll
            for (int n = 0; n < 16; n++) {
                p *= r;
                h[n] = fmaf(p, h[n], dtx * Bv[n]);
                y = fmaf(h[n], Cv[n], y);
            }
        } else {
#pragma unroll
            for (int n = 0; n < 16; n++) {
                float dec = __expf(-dt * Av[n]);
                h[n] = fmaf(dec, h[n], dtx * Bv[n]);
                y = fmaf(h[n], Cv[n], y);
            }
        }
        float yv = fmaf(x, Dd, y);
        ushort_t yh, yl;
        split1(yv, yh, yl);
        g_y_h[ro] = yh;
        g_y_l[ro] = yl;
    }
}

// ---------------- launch ----------------
extern "C" void kernel_launch(void* const* d_in, const int* in_sizes, int n_in,
                              void* d_out, int out_size) {
    (void)in_sizes; (void)n_in; (void)out_size;
    const float* x_norm     = (const float*)d_in[0];
    const float* x_proj_w   = (const float*)d_in[1];
    const float* dt_proj_w  = (const float*)d_in[2];
    const float* dt_proj_b  = (const float*)d_in[3];
    const float* B_proj_w   = (const float*)d_in[4];
    const float* C_proj_w   = (const float*)d_in[5];
    const float* A_log      = (const float*)d_in[6];
    const float* Dvec       = (const float*)d_in[7];
    const float* out_proj_w = (const float*)d_in[8];
    float* out = (float*)d_out;

    void *p_xssm, *p_dt;
    void *p_xnh, *p_xnl, *p_w1h, *p_w2h, *p_w3h, *p_yh, *p_yl;
    cudaGetSymbolAddress(&p_xssm, g_xssm);
    cudaGetSymbolAddress(&p_dt, g_dt);
    cudaGetSymbolAddress(&p_xnh, g_xn_h);  cudaGetSymbolAddress(&p_xnl, g_xn_l);
    cudaGetSymbolAddress(&p_w1h, g_w1_h);
    cudaGetSymbolAddress(&p_w2h, g_w2_h);
    cudaGetSymbolAddress(&p_w3h, g_w3_h);
    cudaGetSymbolAddress(&p_yh, g_y_h);    cudaGetSymbolAddress(&p_yl, g_y_l);

    cudaFuncSetAttribute(gemm_mma<0>, cudaFuncAttributeMaxDynamicSharedMemorySize, SM_TOTAL);
    cudaFuncSetAttribute(gemm_mma<1>, cudaFuncAttributeMaxDynamicSharedMemorySize, SM_TOTAL);

    // fp16 split of x_norm; fp16-hi of the three GEMM weights
    {
        int n4 = (CMROWS * CDMODEL) / 4;
        conv_split<<<n4 / 256, 256>>>(x_norm, (ushort_t*)p_xnh, (ushort_t*)p_xnl, n4);
        n4 = (CDMAMBA * CDMODEL) / 4;
        conv_h<<<n4 / 256, 256>>>(x_proj_w, (ushort_t*)p_w1h, n4);
        conv_h<<<n4 / 256, 256>>>(dt_proj_w, (ushort_t*)p_w2h, n4);
        n4 = (CDMAMBA * CDMAMBA) / 4;
        conv_h<<<n4 / 256, 256>>>(out_proj_w, (ushort_t*)p_w3h, n4);
    }

    dim3 gemm_grid(CDMAMBA / 128, CMROWS / 128);   // (16, 64)

    // 1) x_ssm = x_norm @ x_proj_w^T
    gemm_mma<0><<<gemm_grid, 256, SM_TOTAL>>>(
        (const ushort_t*)p_xnh, (const ushort_t*)p_xnl, (const ushort_t*)p_w1h,
        nullptr, (float*)p_xssm, CMROWS, CDMAMBA, CDMODEL);
    // 2) dt = clip(softplus(clip(x_norm @ dt_proj_w^T + b)))
    gemm_mma<1><<<gemm_grid, 256, SM_TOTAL>>>(
        (const ushort_t*)p_xnh, (const ushort_t*)p_xnl, (const ushort_t*)p_w2h,
        dt_proj_b, (float*)p_dt, CMROWS, CDMAMBA, CDMODEL);
    // 3) normalized B, C
    bc_kernel<<<CMROWS / 4, 128>>>(x_norm, B_proj_w, C_proj_w);
    // 4-6) chunked selective scan (pass3 emits y split into fp16 hi/lo)
    dim3 scan_grid(CDMAMBA / 256, CNCHUNK, CBATCH);
    scan_pass1<<<scan_grid, 256>>>(A_log);
    scan_pass2<<<(CBATCH * CDMAMBA) / 256, 256>>>(A_log);
    scan_pass3<<<scan_grid, 256>>>(A_log, Dvec);
    // 7) out = y @ out_proj_w^T
    gemm_mma<0><<<gemm_grid, 256, SM_TOTAL>>>(
        (const ushort_t*)p_yh, (const ushort_t*)p_yl, (const ushort_t*)p_w3h,
        nullptr, out, CMROWS, CDMAMBA, CDMAMBA);
}